// round 5
// baseline (speedup 1.0000x reference)
#include <cuda_runtime.h>
#include <math.h>

#define N       512
#define NBATCH  16
#define NT      8
#define NKX     257            // kx = 0..256 kept (Hermitian symmetry)

// Scratch: row-FFT result, TRANSPOSED + half-spectrum: [b][kx][y], kx<257
__device__ float2 g_rowfft[(size_t)NBATCH * NKX * N];
__device__ float  g_segsum[256];
__device__ float  g_cnt[256];

// ---------------------------------------------------------------------------
// complex helpers
// ---------------------------------------------------------------------------
__device__ __forceinline__ float2 cadd(float2 a, float2 b){ return make_float2(a.x+b.x, a.y+b.y); }
__device__ __forceinline__ float2 csub(float2 a, float2 b){ return make_float2(a.x-b.x, a.y-b.y); }
__device__ __forceinline__ float2 cmul(float2 a, float2 b){ return make_float2(a.x*b.x-a.y*b.y, a.x*b.y+a.y*b.x); }
__device__ __forceinline__ float2 mul_mi(float2 a){ return make_float2(a.y, -a.x); }   // * (-i)

// 8-point DFT, natural order in/out, forward
__device__ __forceinline__ void fft8(float2 v[8]) {
    float2 t0, t1, t2, t3, t3m;
    t0 = cadd(v[0], v[4]); t1 = csub(v[0], v[4]);
    t2 = cadd(v[2], v[6]); t3 = csub(v[2], v[6]);
    float2 E0 = cadd(t0, t2), E2 = csub(t0, t2);
    t3m = mul_mi(t3);
    float2 E1 = cadd(t1, t3m), E3 = csub(t1, t3m);
    t0 = cadd(v[1], v[5]); t1 = csub(v[1], v[5]);
    t2 = cadd(v[3], v[7]); t3 = csub(v[3], v[7]);
    float2 O0 = cadd(t0, t2), O2 = csub(t0, t2);
    t3m = mul_mi(t3);
    float2 O1 = cadd(t1, t3m), O3 = csub(t1, t3m);
    const float C = 0.7071067811865476f;
    float2 O1w = make_float2(C*(O1.x + O1.y), C*(O1.y - O1.x));
    float2 O2w = mul_mi(O2);
    float2 O3w = make_float2(C*(O3.y - O3.x), -C*(O3.x + O3.y));
    v[0] = cadd(E0, O0);  v[4] = csub(E0, O0);
    v[1] = cadd(E1, O1w); v[5] = csub(E1, O1w);
    v[2] = cadd(E2, O2w); v[6] = csub(E2, O2w);
    v[3] = cadd(E3, O3w); v[7] = csub(E3, O3w);
}

// ---------------------------------------------------------------------------
// 512-pt FFT, 64 threads (gt = 0..63), 8 elems/thread, radix-8^3 DIF.
// Input: v[j] = x[gt + 64*j]. Output: thread (m=gt>>3, u=gt&7) holds
// X[64*s + 8*u + m] in v[s].  gre/gim: 512-float staging (per group).
// All groups in the block run lockstep (shared __syncthreads).
// ---------------------------------------------------------------------------
__device__ __forceinline__ void fft512(float2 v[8], int gt,
                                       float* __restrict__ gre, float* __restrict__ gim,
                                       const float* __restrict__ tre, const float* __restrict__ tim) {
    fft8(v);
#pragma unroll
    for (int m = 1; m < 8; m++) {
        int k = gt * m;
        v[m] = cmul(v[m], make_float2(tre[k], tim[k]));
    }
#pragma unroll
    for (int m = 0; m < 8; m++) {
        int idx = m * 64 + (gt ^ (m << 3));
        gre[idx] = v[m].x; gim[idx] = v[m].y;
    }
    __syncthreads();
    {
        int m = gt >> 3, p = gt & 7;
#pragma unroll
        for (int i = 0; i < 8; i++) {
            int idx = m * 64 + p + (((i ^ m) & 7) << 3);
            v[i] = make_float2(gre[idx], gim[idx]);
        }
        fft8(v);
#pragma unroll
        for (int u = 1; u < 8; u++) {
            int k = (p * u) << 3;
            v[u] = cmul(v[u], make_float2(tre[k], tim[k]));
        }
        __syncthreads();
#pragma unroll
        for (int u = 0; u < 8; u++) {
            int idx = m * 64 + (((u ^ m) & 7) << 3) + (p ^ (u & 3));
            gre[idx] = v[u].x; gim[idx] = v[u].y;
        }
    }
    __syncthreads();
    {
        int m = gt >> 3, u = gt & 7;
#pragma unroll
        for (int p = 0; p < 8; p++) {
            int idx = m * 64 + (((u ^ m) & 7) << 3) + (p ^ (u & 3));
            v[p] = make_float2(gre[idx], gim[idx]);
        }
        fft8(v);
    }
}

// ---------------------------------------------------------------------------
// K1: mean over T + row FFT (radix-8), transposed half-spectrum write.
// 256 threads = 4 FFT groups of 64; block covers 4 rows.
// grid = NBATCH * 128 blocks.
// ---------------------------------------------------------------------------
__global__ void __launch_bounds__(256) kMeanRowFFT(const float* __restrict__ in) {
    const int tid = threadIdx.x;
    const int r   = tid >> 6;          // row in block (0..3)
    const int gt  = tid & 63;
    const int b   = blockIdx.x >> 7;
    const int y0  = (blockIdx.x & 127) << 2;

    __shared__ float sre[4 * 512];
    __shared__ float sim[4 * 512];
    __shared__ float tre[512];
    __shared__ float tim[512];

    // issue the global loads FIRST (hide behind twiddle computation)
    float2 v[8];
    const float* base = in + (((size_t)b * NT) * N + (y0 + r)) * N + gt;
#pragma unroll
    for (int j = 0; j < 8; j++) {
        float sa = 0.0f;
#pragma unroll
        for (int t = 0; t < NT; t++) sa += base[(size_t)t * N * N + (j << 6)];
        v[j] = make_float2(sa * 0.125f, 0.0f);
    }

    {
        float s, c;
        sincosf(-6.283185307179586f * (float)tid / 512.0f, &s, &c);
        tre[tid] = c; tim[tid] = s;
        sincosf(-6.283185307179586f * (float)(tid + 256) / 512.0f, &s, &c);
        tre[tid + 256] = c; tim[tid + 256] = s;
    }
    if (blockIdx.x == 0) { g_segsum[tid] = 0.0f; g_cnt[tid] = 0.0f; }
    __syncthreads();

    fft512(v, gt, sre + r * 512, sim + r * 512, tre, tim);

    __syncthreads();   // stage-C reads done; reuse staging for transpose
    // restage swizzled: sre[kx*4 + (r ^ (u&3))], u = (kx>>3)&7
    {
        int m = gt >> 3, u = gt & 7;
#pragma unroll
        for (int s = 0; s < 8; s++) {
            int kx  = (s << 6) + (u << 3) + m;
            int idx = (kx << 2) + (r ^ (u & 3));
            sre[idx] = v[s].x; sim[idx] = v[s].y;
        }
    }
    __syncthreads();

    // global write, kx = 0..256 only (Hermitian half)
    const int y_i  = tid & 3;
    const int kx_i = tid >> 2;         // 0..63
    float2* outp = g_rowfft + (size_t)b * NKX * N + y0 + y_i;
#pragma unroll
    for (int c5 = 0; c5 < 5; c5++) {
        int kx = kx_i + (c5 << 6);
        if (kx <= 256) {
            int uu  = (kx >> 3) & 7;
            int idx = (kx << 2) + (y_i ^ (uu & 3));
            outp[(size_t)kx * N] = make_float2(sre[idx], sim[idx]);
        }
    }
}

// ---------------------------------------------------------------------------
// K2: column FFT per (kx, batch-octet). grid = (257, 2), 512 threads.
// 8 groups of 64, each does ONE batch's column FFT; |F|^2 radially binned
// with Hermitian weight.
// ---------------------------------------------------------------------------
__global__ void __launch_bounds__(512) kColFFTPower() {
    const int tid = threadIdx.x;
    const int g   = tid >> 6;          // group 0..7
    const int gt  = tid & 63;
    const int kx  = blockIdx.x;        // 0..256
    const int b   = (blockIdx.y << 3) + g;

    __shared__ float sre[8 * 512];
    __shared__ float sim[8 * 512];
    __shared__ float tre[512];
    __shared__ float tim[512];
    __shared__ float bins[256];
    __shared__ float cbin[256];

    // prefetch loads before any barrier
    const float2* col = g_rowfft + ((size_t)b * NKX + kx) * N;
    float2 v[8];
#pragma unroll
    for (int j = 0; j < 8; j++) v[j] = col[gt + (j << 6)];

    {
        float s, c;
        sincosf(-6.283185307179586f * (float)tid / 512.0f, &s, &c);
        tre[tid] = c; tim[tid] = s;
    }
    if (tid < 256) { bins[tid] = 0.0f; cbin[tid] = 0.0f; }
    __syncthreads();

    fft512(v, gt, sre + g * 512, sim + g * 512, tre, tim);

    // radial binning: thread (m,u) owns ky = 64s+8u+m
    {
        const float w     = (kx == 0 || kx == 256) ? 1.0f : 2.0f;
        const float fdx2  = (float)((kx - 256) * (kx - 256));
        const bool  doCnt = (blockIdx.y == 0) && (g == 0);
        int m = gt >> 3, u = gt & 7;
#pragma unroll
        for (int s = 0; s < 8; s++) {
            int ky = (s << 6) + (u << 3) + m;
            int dy = ky - 256;
            int rr = (int)sqrtf(fdx2 + (float)(dy * dy));
            if (rr >= 1 && rr < 256) {
                atomicAdd(&bins[rr], w * (v[s].x * v[s].x + v[s].y * v[s].y));
                if (doCnt) atomicAdd(&cbin[rr], w);
            }
        }
    }
    __syncthreads();

    if (tid >= 1 && tid < 256) {
        if (bins[tid] != 0.0f) atomicAdd(&g_segsum[tid], bins[tid]);
        if (cbin[tid] != 0.0f) atomicAdd(&g_cnt[tid],    cbin[tid]);
    }
}

// ---------------------------------------------------------------------------
// K3: normalization + loss — single warp, shuffle reductions, no barriers
// ---------------------------------------------------------------------------
__global__ void kFinal(float* __restrict__ out) {
    const int lane = threadIdx.x;      // 0..31
    float gv[8], rv[8];
    float gl = 0.0f, rl = 0.0f;
#pragma unroll
    for (int i = 0; i < 8; i++) {
        int r = (i << 5) + lane;
        float g = 0.0f, rk = 0.0f;
        if (r >= 1) {
            float c = g_cnt[r];
            if (c > 0.0f) g = g_segsum[r] / (fmaxf(c, 1.0f) * 16.0f);   // B*C
            rk = __powf((float)r, -5.0f / 3.0f);
        }
        gv[i] = g; rv[i] = rk;
        gl += g;  rl += rk;
    }
#pragma unroll
    for (int o = 16; o > 0; o >>= 1) {
        gl += __shfl_xor_sync(0xFFFFFFFFu, gl, o);
        rl += __shfl_xor_sync(0xFFFFFFFFu, rl, o);
    }
    float d = 0.0f;
#pragma unroll
    for (int i = 0; i < 8; i++) {
        if (((i << 5) + lane) >= 1) {
            float gn = gv[i] / (gl + 1e-8f);
            float rn = rv[i] / (rl + 1e-8f);
            d += (gn - rn) * (gn - rn);
        }
    }
#pragma unroll
    for (int o = 16; o > 0; o >>= 1) d += __shfl_xor_sync(0xFFFFFFFFu, d, o);
    if (lane == 0) out[0] = d / 255.0f;
}

// ---------------------------------------------------------------------------
extern "C" void kernel_launch(void* const* d_in, const int* in_sizes, int n_in,
                              void* d_out, int out_size) {
    const float* in  = (const float*)d_in[0];
    float*       out = (float*)d_out;

    kMeanRowFFT<<<NBATCH * 128, 256>>>(in);
    dim3 g2(NKX, 2);
    kColFFTPower<<<g2, 512>>>();
    kFinal<<<1, 32>>>(out);
}

// round 6
// speedup vs baseline: 1.0556x; 1.0556x over previous
#include <cuda_runtime.h>
#include <math.h>

#define N       512
#define NBATCH  16
#define NT      8
#define NKX     257            // kx = 0..256 kept (Hermitian symmetry)
#define NSEG    8              // replicated bin arrays (atomic spread)

// Scratch: row-FFT result, TRANSPOSED + half-spectrum: [b][kx][y], kx<257
__device__ float2 g_rowfft[(size_t)NBATCH * NKX * N];
__device__ float  g_seg8[NSEG * 256];
__device__ float  g_cnt[256];

// ---------------------------------------------------------------------------
// complex helpers
// ---------------------------------------------------------------------------
__device__ __forceinline__ float2 cadd(float2 a, float2 b){ return make_float2(a.x+b.x, a.y+b.y); }
__device__ __forceinline__ float2 csub(float2 a, float2 b){ return make_float2(a.x-b.x, a.y-b.y); }
__device__ __forceinline__ float2 cmul(float2 a, float2 b){ return make_float2(a.x*b.x-a.y*b.y, a.x*b.y+a.y*b.x); }
__device__ __forceinline__ float2 mul_mi(float2 a){ return make_float2(a.y, -a.x); }   // * (-i)

// 8-point DFT, natural order in/out, forward
__device__ __forceinline__ void fft8(float2 v[8]) {
    float2 t0, t1, t2, t3, t3m;
    t0 = cadd(v[0], v[4]); t1 = csub(v[0], v[4]);
    t2 = cadd(v[2], v[6]); t3 = csub(v[2], v[6]);
    float2 E0 = cadd(t0, t2), E2 = csub(t0, t2);
    t3m = mul_mi(t3);
    float2 E1 = cadd(t1, t3m), E3 = csub(t1, t3m);
    t0 = cadd(v[1], v[5]); t1 = csub(v[1], v[5]);
    t2 = cadd(v[3], v[7]); t3 = csub(v[3], v[7]);
    float2 O0 = cadd(t0, t2), O2 = csub(t0, t2);
    t3m = mul_mi(t3);
    float2 O1 = cadd(t1, t3m), O3 = csub(t1, t3m);
    const float C = 0.7071067811865476f;
    float2 O1w = make_float2(C*(O1.x + O1.y), C*(O1.y - O1.x));
    float2 O2w = mul_mi(O2);
    float2 O3w = make_float2(C*(O3.y - O3.x), -C*(O3.x + O3.y));
    v[0] = cadd(E0, O0);  v[4] = csub(E0, O0);
    v[1] = cadd(E1, O1w); v[5] = csub(E1, O1w);
    v[2] = cadd(E2, O2w); v[6] = csub(E2, O2w);
    v[3] = cadd(E3, O3w); v[7] = csub(E3, O3w);
}

// ---------------------------------------------------------------------------
// 512-pt FFT, 64 threads (gt = 0..63), 8 elems/thread, radix-8^3 DIF.
// Input: v[j] = x[gt + 64*j]. Output: thread (m=gt>>3, u=gt&7) holds
// X[64*s + 8*u + m] in v[s].  gre/gim: 512-float staging (per group).
// All groups in the block run lockstep (shared __syncthreads).
// ---------------------------------------------------------------------------
__device__ __forceinline__ void fft512(float2 v[8], int gt,
                                       float* __restrict__ gre, float* __restrict__ gim,
                                       const float* __restrict__ tre, const float* __restrict__ tim) {
    fft8(v);
#pragma unroll
    for (int m = 1; m < 8; m++) {
        int k = gt * m;
        v[m] = cmul(v[m], make_float2(tre[k], tim[k]));
    }
#pragma unroll
    for (int m = 0; m < 8; m++) {
        int idx = m * 64 + (gt ^ (m << 3));
        gre[idx] = v[m].x; gim[idx] = v[m].y;
    }
    __syncthreads();
    {
        int m = gt >> 3, p = gt & 7;
#pragma unroll
        for (int i = 0; i < 8; i++) {
            int idx = m * 64 + p + (((i ^ m) & 7) << 3);
            v[i] = make_float2(gre[idx], gim[idx]);
        }
        fft8(v);
#pragma unroll
        for (int u = 1; u < 8; u++) {
            int k = (p * u) << 3;
            v[u] = cmul(v[u], make_float2(tre[k], tim[k]));
        }
        __syncthreads();
#pragma unroll
        for (int u = 0; u < 8; u++) {
            int idx = m * 64 + (((u ^ m) & 7) << 3) + (p ^ (u & 3));
            gre[idx] = v[u].x; gim[idx] = v[u].y;
        }
    }
    __syncthreads();
    {
        int m = gt >> 3, u = gt & 7;
#pragma unroll
        for (int p = 0; p < 8; p++) {
            int idx = m * 64 + (((u ^ m) & 7) << 3) + (p ^ (u & 3));
            v[p] = make_float2(gre[idx], gim[idx]);
        }
        fft8(v);
    }
}

// ---------------------------------------------------------------------------
// K1: mean over T + row FFT (radix-8), transposed half-spectrum write.
// 256 threads = 4 FFT groups of 64; block covers 4 rows.
// grid = NBATCH * 128 blocks.   (measured best: 29.2us)
// ---------------------------------------------------------------------------
__global__ void __launch_bounds__(256) kMeanRowFFT(const float* __restrict__ in) {
    const int tid = threadIdx.x;
    const int r   = tid >> 6;          // row in block (0..3)
    const int gt  = tid & 63;
    const int b   = blockIdx.x >> 7;
    const int y0  = (blockIdx.x & 127) << 2;

    __shared__ float sre[4 * 512];
    __shared__ float sim[4 * 512];
    __shared__ float tre[512];
    __shared__ float tim[512];

    // issue the global loads FIRST (hide behind twiddle computation)
    float2 v[8];
    const float* base = in + (((size_t)b * NT) * N + (y0 + r)) * N + gt;
#pragma unroll
    for (int j = 0; j < 8; j++) {
        float sa = 0.0f;
#pragma unroll
        for (int t = 0; t < NT; t++) sa += base[(size_t)t * N * N + (j << 6)];
        v[j] = make_float2(sa * 0.125f, 0.0f);
    }

    {
        float s, c;
        sincosf(-6.283185307179586f * (float)tid / 512.0f, &s, &c);
        tre[tid] = c; tim[tid] = s;
        sincosf(-6.283185307179586f * (float)(tid + 256) / 512.0f, &s, &c);
        tre[tid + 256] = c; tim[tid + 256] = s;
    }
    if (blockIdx.x == 0) {
#pragma unroll
        for (int q = 0; q < NSEG; q++) g_seg8[q * 256 + tid] = 0.0f;
        g_cnt[tid] = 0.0f;
    }
    __syncthreads();

    fft512(v, gt, sre + r * 512, sim + r * 512, tre, tim);

    __syncthreads();   // stage-C reads done; reuse staging for transpose
    // restage swizzled: sre[kx*4 + (r ^ (u&3))], u = (kx>>3)&7
    {
        int m = gt >> 3, u = gt & 7;
#pragma unroll
        for (int s = 0; s < 8; s++) {
            int kx  = (s << 6) + (u << 3) + m;
            int idx = (kx << 2) + (r ^ (u & 3));
            sre[idx] = v[s].x; sim[idx] = v[s].y;
        }
    }
    __syncthreads();

    // global write, kx = 0..256 only (Hermitian half)
    const int y_i  = tid & 3;
    const int kx_i = tid >> 2;         // 0..63
    float2* outp = g_rowfft + (size_t)b * NKX * N + y0 + y_i;
#pragma unroll
    for (int c5 = 0; c5 < 5; c5++) {
        int kx = kx_i + (c5 << 6);
        if (kx <= 256) {
            int uu  = (kx >> 3) & 7;
            int idx = (kx << 2) + (y_i ^ (uu & 3));
            outp[(size_t)kx * N] = make_float2(sre[idx], sim[idx]);
        }
    }
}

// ---------------------------------------------------------------------------
// K2: column FFT per (kx, batch-quad). grid = (257, 4), 256 threads.
// 4 groups of 64, each does ONE batch's column FFT in a single round.
// |F|^2 binned radially (Hermitian weight) into shared bins, then flushed
// into one of 8 replica arrays (kx & 7) to spread atomic contention.
// ---------------------------------------------------------------------------
__global__ void __launch_bounds__(256) kColFFTPower() {
    const int tid = threadIdx.x;
    const int g   = tid >> 6;          // group 0..3
    const int gt  = tid & 63;
    const int kx  = blockIdx.x;        // 0..256
    const int b   = (blockIdx.y << 2) + g;

    __shared__ float sre[4 * 512];
    __shared__ float sim[4 * 512];
    __shared__ float tre[512];
    __shared__ float tim[512];
    __shared__ float bins[256];
    __shared__ float cbin[256];

    // prefetch loads before any barrier
    const float2* col = g_rowfft + ((size_t)b * NKX + kx) * N;
    float2 v[8];
#pragma unroll
    for (int j = 0; j < 8; j++) v[j] = col[gt + (j << 6)];

    {
        float s, c;
        sincosf(-6.283185307179586f * (float)tid / 512.0f, &s, &c);
        tre[tid] = c; tim[tid] = s;
        sincosf(-6.283185307179586f * (float)(tid + 256) / 512.0f, &s, &c);
        tre[tid + 256] = c; tim[tid + 256] = s;
        bins[tid] = 0.0f; cbin[tid] = 0.0f;
    }
    __syncthreads();

    fft512(v, gt, sre + g * 512, sim + g * 512, tre, tim);

    // radial binning: thread (m,u) owns ky = 64s+8u+m
    {
        const float w     = (kx == 0 || kx == 256) ? 1.0f : 2.0f;
        const float fdx2  = (float)((kx - 256) * (kx - 256));
        const bool  doCnt = (blockIdx.y == 0) && (g == 0);
        int m = gt >> 3, u = gt & 7;
#pragma unroll
        for (int s = 0; s < 8; s++) {
            int ky = (s << 6) + (u << 3) + m;
            int dy = ky - 256;
            int rr = (int)sqrtf(fdx2 + (float)(dy * dy));
            if (rr >= 1 && rr < 256) {
                atomicAdd(&bins[rr], w * (v[s].x * v[s].x + v[s].y * v[s].y));
                if (doCnt) atomicAdd(&cbin[rr], w);
            }
        }
    }
    __syncthreads();

    float* segslot = g_seg8 + ((kx & 7) << 8);
    if (tid >= 1) {
        if (bins[tid] != 0.0f) atomicAdd(&segslot[tid], bins[tid]);
        if (cbin[tid] != 0.0f) atomicAdd(&g_cnt[tid],   cbin[tid]);
    }
}

// ---------------------------------------------------------------------------
// K3: normalization + loss — single warp, shuffle reductions, no barriers
// ---------------------------------------------------------------------------
__global__ void kFinal(float* __restrict__ out) {
    const int lane = threadIdx.x;      // 0..31
    float gv[8], rv[8];
    float gl = 0.0f, rl = 0.0f;
#pragma unroll
    for (int i = 0; i < 8; i++) {
        int r = (i << 5) + lane;
        float g = 0.0f, rk = 0.0f;
        if (r >= 1) {
            float seg = 0.0f;
#pragma unroll
            for (int q = 0; q < NSEG; q++) seg += g_seg8[(q << 8) + r];
            float c = g_cnt[r];
            if (c > 0.0f) g = seg / (fmaxf(c, 1.0f) * 16.0f);   // B*C
            rk = __powf((float)r, -5.0f / 3.0f);
        }
        gv[i] = g; rv[i] = rk;
        gl += g;  rl += rk;
    }
#pragma unroll
    for (int o = 16; o > 0; o >>= 1) {
        gl += __shfl_xor_sync(0xFFFFFFFFu, gl, o);
        rl += __shfl_xor_sync(0xFFFFFFFFu, rl, o);
    }
    float d = 0.0f;
#pragma unroll
    for (int i = 0; i < 8; i++) {
        if (((i << 5) + lane) >= 1) {
            float gn = gv[i] / (gl + 1e-8f);
            float rn = rv[i] / (rl + 1e-8f);
            d += (gn - rn) * (gn - rn);
        }
    }
#pragma unroll
    for (int o = 16; o > 0; o >>= 1) d += __shfl_xor_sync(0xFFFFFFFFu, d, o);
    if (lane == 0) out[0] = d / 255.0f;
}

// ---------------------------------------------------------------------------
extern "C" void kernel_launch(void* const* d_in, const int* in_sizes, int n_in,
                              void* d_out, int out_size) {
    const float* in  = (const float*)d_in[0];
    float*       out = (float*)d_out;

    kMeanRowFFT<<<NBATCH * 128, 256>>>(in);
    dim3 g2(NKX, 4);
    kColFFTPower<<<g2, 256>>>();
    kFinal<<<1, 32>>>(out);
}

// round 8
// speedup vs baseline: 1.0774x; 1.0206x over previous
#include <cuda_runtime.h>
#include <math.h>

#define N       512
#define NBATCH  16
#define NT      8
#define NKX     257            // kx = 0..256 kept (Hermitian symmetry)
#define NSEG    8              // replicated bin arrays (atomic spread)

// Scratch: row-FFT result, TRANSPOSED + half-spectrum: [b][kx][y], kx<257
__device__ float2 g_rowfft[(size_t)NBATCH * NKX * N];
__device__ float  g_seg8[NSEG * 256];
__device__ float  g_cnt[256];
__device__ float  g_twre[512];
__device__ float  g_twim[512];

// ---------------------------------------------------------------------------
// complex helpers
// ---------------------------------------------------------------------------
__device__ __forceinline__ float2 cadd(float2 a, float2 b){ return make_float2(a.x+b.x, a.y+b.y); }
__device__ __forceinline__ float2 csub(float2 a, float2 b){ return make_float2(a.x-b.x, a.y-b.y); }
__device__ __forceinline__ float2 cmul(float2 a, float2 b){ return make_float2(a.x*b.x-a.y*b.y, a.x*b.y+a.y*b.x); }
__device__ __forceinline__ float2 mul_mi(float2 a){ return make_float2(a.y, -a.x); }   // * (-i)

// 8-point DFT, natural order in/out, forward
__device__ __forceinline__ void fft8(float2 v[8]) {
    float2 t0, t1, t2, t3, t3m;
    t0 = cadd(v[0], v[4]); t1 = csub(v[0], v[4]);
    t2 = cadd(v[2], v[6]); t3 = csub(v[2], v[6]);
    float2 E0 = cadd(t0, t2), E2 = csub(t0, t2);
    t3m = mul_mi(t3);
    float2 E1 = cadd(t1, t3m), E3 = csub(t1, t3m);
    t0 = cadd(v[1], v[5]); t1 = csub(v[1], v[5]);
    t2 = cadd(v[3], v[7]); t3 = csub(v[3], v[7]);
    float2 O0 = cadd(t0, t2), O2 = csub(t0, t2);
    t3m = mul_mi(t3);
    float2 O1 = cadd(t1, t3m), O3 = csub(t1, t3m);
    const float C = 0.7071067811865476f;
    float2 O1w = make_float2(C*(O1.x + O1.y), C*(O1.y - O1.x));
    float2 O2w = mul_mi(O2);
    float2 O3w = make_float2(C*(O3.y - O3.x), -C*(O3.x + O3.y));
    v[0] = cadd(E0, O0);  v[4] = csub(E0, O0);
    v[1] = cadd(E1, O1w); v[5] = csub(E1, O1w);
    v[2] = cadd(E2, O2w); v[6] = csub(E2, O2w);
    v[3] = cadd(E3, O3w); v[7] = csub(E3, O3w);
}

// ---------------------------------------------------------------------------
// 512-pt FFT, 64 threads (gt = 0..63), 8 elems/thread, radix-8^3 DIF.
// Input: v[j] = x[gt + 64*j]. Output: thread (m=gt>>3, u=gt&7) holds
// X[64*s + 8*u + m] in v[s].  gre/gim: 512-float staging (per group).
// All groups in the block run lockstep (shared __syncthreads).
// ---------------------------------------------------------------------------
__device__ __forceinline__ void fft512(float2 v[8], int gt,
                                       float* __restrict__ gre, float* __restrict__ gim,
                                       const float* __restrict__ tre, const float* __restrict__ tim) {
    fft8(v);
#pragma unroll
    for (int m = 1; m < 8; m++) {
        int k = gt * m;
        v[m] = cmul(v[m], make_float2(tre[k], tim[k]));
    }
#pragma unroll
    for (int m = 0; m < 8; m++) {
        int idx = m * 64 + (gt ^ (m << 3));
        gre[idx] = v[m].x; gim[idx] = v[m].y;
    }
    __syncthreads();
    {
        int m = gt >> 3, p = gt & 7;
#pragma unroll
        for (int i = 0; i < 8; i++) {
            int idx = m * 64 + p + (((i ^ m) & 7) << 3);
            v[i] = make_float2(gre[idx], gim[idx]);
        }
        fft8(v);
#pragma unroll
        for (int u = 1; u < 8; u++) {
            int k = (p * u) << 3;
            v[u] = cmul(v[u], make_float2(tre[k], tim[k]));
        }
        __syncthreads();
#pragma unroll
        for (int u = 0; u < 8; u++) {
            int idx = m * 64 + (((u ^ m) & 7) << 3) + (p ^ (u & 3));
            gre[idx] = v[u].x; gim[idx] = v[u].y;
        }
    }
    __syncthreads();
    {
        int m = gt >> 3, u = gt & 7;
#pragma unroll
        for (int p = 0; p < 8; p++) {
            int idx = m * 64 + (((u ^ m) & 7) << 3) + (p ^ (u & 3));
            v[p] = make_float2(gre[idx], gim[idx]);
        }
        fft8(v);
    }
}

// copy twiddle table from global to smem: 256 threads, 1 float4 each
__device__ __forceinline__ void load_twiddles(int tid, float* tre, float* tim) {
    const float4* src = (tid < 128) ? (const float4*)g_twre : (const float4*)g_twim;
    float*        dst = (tid < 128) ? tre : tim;
    int i = tid & 127;
    ((float4*)dst)[i] = src[i];
}

// ---------------------------------------------------------------------------
// kInit: twiddle table + zero bins (1 block, 256 threads)
// ---------------------------------------------------------------------------
__global__ void kInit() {
    const int tid = threadIdx.x;
    float s, c;
    sincosf(-6.283185307179586f * (float)tid / 512.0f, &s, &c);
    g_twre[tid] = c; g_twim[tid] = s;
    sincosf(-6.283185307179586f * (float)(tid + 256) / 512.0f, &s, &c);
    g_twre[tid + 256] = c; g_twim[tid + 256] = s;
#pragma unroll
    for (int q = 0; q < NSEG; q++) g_seg8[q * 256 + tid] = 0.0f;
    g_cnt[tid] = 0.0f;
}

// ---------------------------------------------------------------------------
// K1: mean over T + row FFT (radix-8), transposed half-spectrum write.
// 256 threads = 4 FFT groups of 64; block covers 4 rows.
// grid = NBATCH * 128 blocks.
// ---------------------------------------------------------------------------
__global__ void __launch_bounds__(256) kMeanRowFFT(const float* __restrict__ in) {
    const int tid = threadIdx.x;
    const int r   = tid >> 6;          // row in block (0..3)
    const int gt  = tid & 63;
    const int b   = blockIdx.x >> 7;
    const int y0  = (blockIdx.x & 127) << 2;

    __shared__ float sre[4 * 512];
    __shared__ float sim[4 * 512];
    __shared__ float tre[512];
    __shared__ float tim[512];

    // issue the global loads FIRST (hide behind twiddle copy)
    float2 v[8];
    const float* base = in + (((size_t)b * NT) * N + (y0 + r)) * N + gt;
#pragma unroll
    for (int j = 0; j < 8; j++) {
        float sa = 0.0f;
#pragma unroll
        for (int t = 0; t < NT; t++) sa += base[(size_t)t * N * N + (j << 6)];
        v[j] = make_float2(sa * 0.125f, 0.0f);
    }

    load_twiddles(tid, tre, tim);
    __syncthreads();

    fft512(v, gt, sre + r * 512, sim + r * 512, tre, tim);

    __syncthreads();   // stage-C reads done; reuse staging for transpose
    // restage swizzled: sre[kx*4 + (r ^ (u&3))], u = (kx>>3)&7
    {
        int m = gt >> 3, u = gt & 7;
#pragma unroll
        for (int s = 0; s < 8; s++) {
            int kx  = (s << 6) + (u << 3) + m;
            int idx = (kx << 2) + (r ^ (u & 3));
            sre[idx] = v[s].x; sim[idx] = v[s].y;
        }
    }
    __syncthreads();

    // global write, kx = 0..256 only (Hermitian half)
    const int y_i  = tid & 3;
    const int kx_i = tid >> 2;         // 0..63
    float2* outp = g_rowfft + (size_t)b * NKX * N + y0 + y_i;
#pragma unroll
    for (int c5 = 0; c5 < 5; c5++) {
        int kx = kx_i + (c5 << 6);
        if (kx <= 256) {
            int uu  = (kx >> 3) & 7;
            int idx = (kx << 2) + (y_i ^ (uu & 3));
            outp[(size_t)kx * N] = make_float2(sre[idx], sim[idx]);
        }
    }
}

// ---------------------------------------------------------------------------
// K2: column FFT per (kx, batch-quad). grid = (257, 4), 256 threads.
// 4 groups of 64, each does ONE batch's column FFT in a single round.
// |F|^2 binned radially (Hermitian weight) into shared bins, flushed into
// one of 8 replica arrays (kx & 7).
// ---------------------------------------------------------------------------
__global__ void __launch_bounds__(256) kColFFTPower() {
    const int tid = threadIdx.x;
    const int g   = tid >> 6;          // group 0..3
    const int gt  = tid & 63;
    const int kx  = blockIdx.x;        // 0..256
    const int b   = (blockIdx.y << 2) + g;

    __shared__ float sre[4 * 512];
    __shared__ float sim[4 * 512];
    __shared__ float tre[512];
    __shared__ float tim[512];
    __shared__ float bins[256];
    __shared__ float cbin[256];

    // prefetch loads before any barrier
    const float2* col = g_rowfft + ((size_t)b * NKX + kx) * N;
    float2 v[8];
#pragma unroll
    for (int j = 0; j < 8; j++) v[j] = col[gt + (j << 6)];

    load_twiddles(tid, tre, tim);
    bins[tid] = 0.0f; cbin[tid] = 0.0f;
    __syncthreads();

    fft512(v, gt, sre + g * 512, sim + g * 512, tre, tim);

    // radial binning: thread (m,u) owns ky = 64s+8u+m
    {
        const float w     = (kx == 0 || kx == 256) ? 1.0f : 2.0f;
        const float fdx2  = (float)((kx - 256) * (kx - 256));
        const bool  doCnt = (blockIdx.y == 0) && (g == 0);
        int m = gt >> 3, u = gt & 7;
#pragma unroll
        for (int s = 0; s < 8; s++) {
            int ky = (s << 6) + (u << 3) + m;
            int dy = ky - 256;
            int rr = (int)sqrtf(fdx2 + (float)(dy * dy));
            if (rr >= 1 && rr < 256) {
                atomicAdd(&bins[rr], w * (v[s].x * v[s].x + v[s].y * v[s].y));
                if (doCnt) atomicAdd(&cbin[rr], w);
            }
        }
    }
    __syncthreads();

    float* segslot = g_seg8 + ((kx & 7) << 8);
    if (tid >= 1) {
        if (bins[tid] != 0.0f) atomicAdd(&segslot[tid], bins[tid]);
        if (cbin[tid] != 0.0f) atomicAdd(&g_cnt[tid],   cbin[tid]);
    }
}

// ---------------------------------------------------------------------------
// K3: normalization + loss — single warp, shuffle reductions, no barriers
// ---------------------------------------------------------------------------
__global__ void kFinal(float* __restrict__ out) {
    const int lane = threadIdx.x;      // 0..31
    float gv[8], rv[8];
    float gl = 0.0f, rl = 0.0f;
#pragma unroll
    for (int i = 0; i < 8; i++) {
        int r = (i << 5) + lane;
        float g = 0.0f, rk = 0.0f;
        if (r >= 1) {
            float seg = 0.0f;
#pragma unroll
            for (int q = 0; q < NSEG; q++) seg += g_seg8[(q << 8) + r];
            float c = g_cnt[r];
            if (c > 0.0f) g = seg / (fmaxf(c, 1.0f) * 16.0f);   // B*C
            rk = __powf((float)r, -5.0f / 3.0f);
        }
        gv[i] = g; rv[i] = rk;
        gl += g;  rl += rk;
    }
#pragma unroll
    for (int o = 16; o > 0; o >>= 1) {
        gl += __shfl_xor_sync(0xFFFFFFFFu, gl, o);
        rl += __shfl_xor_sync(0xFFFFFFFFu, rl, o);
    }
    float d = 0.0f;
#pragma unroll
    for (int i = 0; i < 8; i++) {
        if (((i << 5) + lane) >= 1) {
            float gn = gv[i] / (gl + 1e-8f);
            float rn = rv[i] / (rl + 1e-8f);
            d += (gn - rn) * (gn - rn);
        }
    }
#pragma unroll
    for (int o = 16; o > 0; o >>= 1) d += __shfl_xor_sync(0xFFFFFFFFu, d, o);
    if (lane == 0) out[0] = d / 255.0f;
}

// ---------------------------------------------------------------------------
extern "C" void kernel_launch(void* const* d_in, const int* in_sizes, int n_in,
                              void* d_out, int out_size) {
    const float* in  = (const float*)d_in[0];
    float*       out = (float*)d_out;

    kInit<<<1, 256>>>();
    kMeanRowFFT<<<NBATCH * 128, 256>>>(in);
    dim3 g2(NKX, 4);
    kColFFTPower<<<g2, 256>>>();
    kFinal<<<1, 32>>>(out);
}